// round 2
// baseline (speedup 1.0000x reference)
#include <cuda_runtime.h>

// Problem constants
#define BB 512
#define TT 365
#define CC 10
#define PP 64
#define KK (TT * CC)        // 3650
#define KK2 (KK + TT)       // 4015 augmented K (mx|mask) x (-2proto|psqT)
#define KSPLIT 16
#define KCHUNK 256          // 16*256 = 4096 >= 4015

// Scratch (allocation-free: __device__ globals)
__device__ float g_mx[BB * KK];            // masked input, 7.5 MB
__device__ float g_x2[BB];                 // sum mask*x^2 per b
__device__ float g_psqT[TT * PP];          // [t][p] sum_c proto^2
__device__ float g_part[KSPLIT * BB * PP]; // split-K partials of (-2xp + p2)
__device__ int   g_idx[BB];                // argmin indices

// ---------------------------------------------------------------------------
// prep1: per-b — build mx = x*mask, reduce x2, fuse input/mask passthrough
// ---------------------------------------------------------------------------
__global__ __launch_bounds__(256) void prep1_kernel(
    const float* __restrict__ x, const float* __restrict__ mask,
    float* __restrict__ out_in, float* __restrict__ out_mask)
{
    int b = blockIdx.x;
    int tid = threadIdx.x;
    __shared__ float smask[TT];
    for (int t = tid; t < TT; t += 256) {
        float m = mask[b * TT + t];
        smask[t] = m;
        out_mask[b * TT + t] = m;
    }
    __syncthreads();

    float acc = 0.0f;
    const float* xb = x + (size_t)b * KK;
    float* mxb = g_mx + (size_t)b * KK;
    float* oib = out_in + (size_t)b * KK;
    for (int i = tid; i < KK; i += 256) {
        float xv = xb[i];
        float mv = smask[i / CC];
        float mx = xv * mv;
        mxb[i] = mx;
        oib[i] = xv;
        acc = fmaf(mx, xv, acc);   // mask * x^2
    }
    #pragma unroll
    for (int off = 16; off > 0; off >>= 1)
        acc += __shfl_down_sync(0xffffffffu, acc, off);
    __shared__ float red[8];
    if ((tid & 31) == 0) red[tid >> 5] = acc;
    __syncthreads();
    if (tid < 8) {
        float v = red[tid];
        #pragma unroll
        for (int off = 4; off > 0; off >>= 1)
            v += __shfl_down_sync(0xffu, v, off);
        if (tid == 0) g_x2[b] = v;
    }
}

// ---------------------------------------------------------------------------
// prep2: psqT[t][p] = sum_c proto[p][t][c]^2
// ---------------------------------------------------------------------------
__global__ __launch_bounds__(256) void prep2_kernel(const float* __restrict__ proto)
{
    int lin = blockIdx.x * 256 + threadIdx.x;
    if (lin >= TT * PP) return;
    int p = lin & (PP - 1);
    int t = lin >> 6;   // PP == 64
    const float* pr = proto + (size_t)p * KK + t * CC;
    float s = 0.0f;
    #pragma unroll
    for (int c = 0; c < CC; c++) s = fmaf(pr[c], pr[c], s);
    g_psqT[t * PP + p] = s;
}

// ---------------------------------------------------------------------------
// gemm: augmented split-K
//   part[ks][b][p] = sum_{k in chunk} A'[b][k] * B'[p][k]
//   k <  3650 : A' = mx[b][k],          B' = -2*proto[p][k]
//   k >= 3650 : A' = mask[b][k-3650],   B' = psqT[(k-3650)][p]
// 64x64 tile, 256 threads, 4x4 micro-tile, 32-deep smem stages
// ---------------------------------------------------------------------------
__global__ __launch_bounds__(256) void gemm_kernel(
    const float* __restrict__ proto, const float* __restrict__ mask)
{
    const int mb = blockIdx.x * 64;   // batch tile base
    const int ks = blockIdx.y;        // k-split index
    const int tid = threadIdx.x;
    const int m0 = (tid >> 4) * 4;    // 0..60
    const int p0 = (tid & 15) * 4;    // 0..60

    __shared__ float As[32][68];
    __shared__ float Bs[32][68];

    float acc[4][4];
    #pragma unroll
    for (int i = 0; i < 4; i++)
        #pragma unroll
        for (int j = 0; j < 4; j++) acc[i][j] = 0.0f;

    const int kbeg = ks * KCHUNK;
    const int kend = (kbeg + KCHUNK < KK2) ? (kbeg + KCHUNK) : KK2;

    for (int k0 = kbeg; k0 < kend; k0 += 32) {
        #pragma unroll
        for (int j = 0; j < 8; j++) {
            int l = tid + j * 256;       // 0..2047
            int kk = l & 31;
            int mm = l >> 5;             // 0..63
            int k = k0 + kk;
            float av = 0.0f, bv = 0.0f;
            if (k < KK) {
                av = g_mx[(size_t)(mb + mm) * KK + k];
                bv = -2.0f * proto[(size_t)mm * KK + k];
            } else if (k < kend) {
                int t = k - KK;
                av = mask[(size_t)(mb + mm) * TT + t];
                bv = g_psqT[t * PP + mm];
            }
            As[kk][mm] = av;
            Bs[kk][mm] = bv;
        }
        __syncthreads();
        #pragma unroll
        for (int kk = 0; kk < 32; kk++) {
            float4 a4 = *reinterpret_cast<const float4*>(&As[kk][m0]);
            float4 b4 = *reinterpret_cast<const float4*>(&Bs[kk][p0]);
            float av[4] = {a4.x, a4.y, a4.z, a4.w};
            float bv[4] = {b4.x, b4.y, b4.z, b4.w};
            #pragma unroll
            for (int i = 0; i < 4; i++)
                #pragma unroll
                for (int j = 0; j < 4; j++)
                    acc[i][j] = fmaf(av[i], bv[j], acc[i][j]);
        }
        __syncthreads();
    }

    float* dst = g_part + (size_t)ks * BB * PP;
    #pragma unroll
    for (int i = 0; i < 4; i++) {
        float4 v = make_float4(acc[i][0], acc[i][1], acc[i][2], acc[i][3]);
        *reinterpret_cast<float4*>(&dst[(size_t)(mb + m0 + i) * PP + p0]) = v;
    }
}

// ---------------------------------------------------------------------------
// finalize: d = x2 + sum_ks part; argmin (first-min tie-break); idx/label out
// 4 batches per block, 256 threads (64 per batch)
// ---------------------------------------------------------------------------
__global__ __launch_bounds__(256) void finalize_kernel(
    const int* __restrict__ label,
    float* __restrict__ out_dist, float* __restrict__ out_idx,
    float* __restrict__ out_lab)
{
    int tid = threadIdx.x;
    int bb = tid >> 6;          // 0..3
    int p  = tid & 63;          // 0..63
    int b  = blockIdx.x * 4 + bb;

    float d = g_x2[b];
    #pragma unroll
    for (int ks = 0; ks < KSPLIT; ks++)
        d += g_part[((size_t)ks * BB + b) * PP + p];
    out_dist[b * PP + p] = d;

    // argmin over 64 lanes = 2 warps
    float dv = d;
    unsigned iv = (unsigned)p;
    #pragma unroll
    for (int off = 16; off > 0; off >>= 1) {
        float od = __shfl_down_sync(0xffffffffu, dv, off);
        unsigned oi = __shfl_down_sync(0xffffffffu, iv, off);
        if (od < dv || (od == dv && oi < iv)) { dv = od; iv = oi; }
    }
    __shared__ float rd[8];
    __shared__ unsigned ri[8];
    int w = tid >> 5;
    if ((tid & 31) == 0) { rd[w] = dv; ri[w] = iv; }
    __syncthreads();
    if (p == 0) {
        float d0 = rd[2 * bb]; unsigned i0 = ri[2 * bb];
        float d1 = rd[2 * bb + 1]; unsigned i1 = ri[2 * bb + 1];
        if (d1 < d0 || (d1 == d0 && i1 < i0)) { d0 = d1; i0 = i1; }
        g_idx[b] = (int)i0;
        out_idx[b] = (float)i0;
        out_lab[b] = (float)label[b];
    }
}

// ---------------------------------------------------------------------------
// gather: output_seq[b] = proto[idx[b]]
// ---------------------------------------------------------------------------
__global__ __launch_bounds__(256) void gather_kernel(
    const float* __restrict__ proto, float* __restrict__ out_seq)
{
    int b = blockIdx.x;
    int idx = g_idx[b];
    const float* src = proto + (size_t)idx * KK;
    float* dst = out_seq + (size_t)b * KK;
    for (int i = threadIdx.x; i < KK; i += 256) dst[i] = src[i];
}

// ---------------------------------------------------------------------------
extern "C" void kernel_launch(void* const* d_in, const int* in_sizes, int n_in,
                              void* d_out, int out_size)
{
    const float* x     = (const float*)d_in[0];  // [512,365,10]
    const float* mask  = (const float*)d_in[1];  // [512,365]
    const int*   label = (const int*)  d_in[2];  // [512]
    const float* proto = (const float*)d_in[3];  // [64,365,10]

    float* out = (float*)d_out;
    float* out_seq  = out;                          // [512,365,10]
    float* out_in   = out_seq  + (size_t)BB * KK;   // [512,365,10]
    float* out_dist = out_in   + (size_t)BB * KK;   // [512,64]
    float* out_idx  = out_dist + (size_t)BB * PP;   // [512]
    float* out_lab  = out_idx  + BB;                // [512]
    float* out_mask = out_lab  + BB;                // [512,365]

    prep1_kernel<<<BB, 256>>>(x, mask, out_in, out_mask);
    prep2_kernel<<<(TT * PP + 255) / 256, 256>>>(proto);
    gemm_kernel<<<dim3(BB / 64, KSPLIT), 256>>>(proto, mask);
    finalize_kernel<<<BB / 4, 256>>>(label, out_dist, out_idx, out_lab);
    gather_kernel<<<BB, 256>>>(proto, out_seq);
}

// round 11
// speedup vs baseline: 1.2755x; 1.2755x over previous
#include <cuda_runtime.h>

// Problem constants
#define BB 512
#define TT 365
#define CC 10
#define PP 64
#define KK (TT * CC)        // 3650
#define KK2 (KK + TT)       // 4015 augmented K: (x*mask | mask) x (-2proto | psq)
#define KSPLIT 16
#define KCHUNK 256          // 16*256 = 4096 >= 4015

// Scratch (allocation-free: __device__ globals)
__device__ float g_x2[BB];                 // sum mask*x^2 per b
__device__ float g_psq[PP * TT];           // [p][t] sum_c proto^2  (p-major!)
__device__ float g_part[KSPLIT * BB * PP]; // split-K partials of (-2xp + p2)

// ---------------------------------------------------------------------------
// prep: blocks [0,512): per-b x2 + passthrough copies + label
//       blocks [512,576): per-p prototype row norms g_psq[p][t]
// ---------------------------------------------------------------------------
__global__ __launch_bounds__(256) void prep_kernel(
    const float* __restrict__ x, const float* __restrict__ mask,
    const int* __restrict__ label, const float* __restrict__ proto,
    float* __restrict__ out_in, float* __restrict__ out_mask,
    float* __restrict__ out_lab)
{
    int tid = threadIdx.x;

    if (blockIdx.x < BB) {
        int b = blockIdx.x;
        __shared__ float smask[TT];
        for (int t = tid; t < TT; t += 256) {
            float m = mask[b * TT + t];
            smask[t] = m;
            out_mask[b * TT + t] = m;
        }
        if (tid == 0) out_lab[b] = (float)label[b];
        __syncthreads();

        float acc = 0.0f;
        const float2* xb = (const float2*)(x + (size_t)b * KK);
        float2* oib = (float2*)(out_in + (size_t)b * KK);
        for (int i = tid; i < KK / 2; i += 256) {   // KK even: 1825 float2
            float2 v = xb[i];
            oib[i] = v;
            float m0 = smask[(2 * i) / CC];
            float m1 = smask[(2 * i + 1) / CC];
            acc = fmaf(v.x * m0, v.x, acc);
            acc = fmaf(v.y * m1, v.y, acc);
        }
        #pragma unroll
        for (int off = 16; off > 0; off >>= 1)
            acc += __shfl_down_sync(0xffffffffu, acc, off);
        __shared__ float red[8];
        if ((tid & 31) == 0) red[tid >> 5] = acc;
        __syncthreads();
        if (tid < 8) {
            float v = red[tid];
            #pragma unroll
            for (int off = 4; off > 0; off >>= 1)
                v += __shfl_down_sync(0xffu, v, off);
            if (tid == 0) g_x2[b] = v;
        }
    } else {
        int p = blockIdx.x - BB;        // 0..63
        __shared__ float srow[KK];      // 14.6 KB
        const float* pr = proto + (size_t)p * KK;
        for (int i = tid; i < KK; i += 256) srow[i] = pr[i];
        __syncthreads();
        for (int t = tid; t < TT; t += 256) {
            float s = 0.0f;
            #pragma unroll
            for (int c = 0; c < CC; c++) {
                float v = srow[t * CC + c];
                s = fmaf(v, v, s);
            }
            g_psq[p * TT + t] = s;
        }
    }
}

// ---------------------------------------------------------------------------
// gemm: augmented split-K, on-the-fly masked A
//   part[ks][b][p] = sum_{k in chunk} A'[b][k] * B'[p][k]
//   k <  3650 : A' = x[b][k]*mask[b][k/10],  B' = -2*proto[p][k]
//   k >= 3650 : A' = mask[b][k-3650],        B' = g_psq[p][k-3650]
// 64x64 tile, 256 threads, 4x4 micro-tile, 32-deep smem stages
// ---------------------------------------------------------------------------
__global__ __launch_bounds__(256) void gemm_kernel(
    const float* __restrict__ x, const float* __restrict__ mask,
    const float* __restrict__ proto)
{
    const int mb = blockIdx.x * 64;   // batch tile base
    const int ks = blockIdx.y;        // k-split index
    const int tid = threadIdx.x;
    const int m0 = (tid >> 4) * 4;    // 0..60
    const int p0 = (tid & 15) * 4;    // 0..60

    __shared__ float As[32][68];
    __shared__ float Bs[32][68];

    float acc[4][4];
    #pragma unroll
    for (int i = 0; i < 4; i++)
        #pragma unroll
        for (int j = 0; j < 4; j++) acc[i][j] = 0.0f;

    const int kbeg = ks * KCHUNK;
    const int kend = (kbeg + KCHUNK < KK2) ? (kbeg + KCHUNK) : KK2;

    for (int k0 = kbeg; k0 < kend; k0 += 32) {
        #pragma unroll
        for (int j = 0; j < 8; j++) {
            int l = tid + j * 256;       // 0..2047
            int kk = l & 31;
            int mm = l >> 5;             // 0..63
            int k = k0 + kk;
            float av = 0.0f, bv = 0.0f;
            if (k < KK) {
                int t = (unsigned)k / CC;
                av = x[(size_t)(mb + mm) * KK + k] * mask[(size_t)(mb + mm) * TT + t];
                bv = -2.0f * proto[(size_t)mm * KK + k];
            } else if (k < KK2) {
                int t = k - KK;
                av = mask[(size_t)(mb + mm) * TT + t];
                bv = g_psq[mm * TT + t];   // p-major: coalesced over t
            }
            As[kk][mm] = av;
            Bs[kk][mm] = bv;
        }
        __syncthreads();
        #pragma unroll
        for (int kk = 0; kk < 32; kk++) {
            float4 a4 = *reinterpret_cast<const float4*>(&As[kk][m0]);
            float4 b4 = *reinterpret_cast<const float4*>(&Bs[kk][p0]);
            float av[4] = {a4.x, a4.y, a4.z, a4.w};
            float bv[4] = {b4.x, b4.y, b4.z, b4.w};
            #pragma unroll
            for (int i = 0; i < 4; i++)
                #pragma unroll
                for (int j = 0; j < 4; j++)
                    acc[i][j] = fmaf(av[i], bv[j], acc[i][j]);
        }
        __syncthreads();
    }

    float* dst = g_part + (size_t)ks * BB * PP;
    #pragma unroll
    for (int i = 0; i < 4; i++) {
        float4 v = make_float4(acc[i][0], acc[i][1], acc[i][2], acc[i][3]);
        *reinterpret_cast<float4*>(&dst[(size_t)(mb + m0 + i) * PP + p0]) = v;
    }
}

// ---------------------------------------------------------------------------
// finalize+gather: d = x2 + sum_ks part; argmin; dist/idx out; copy proto[idx]
// 4 batches per block, 256 threads (64 per batch)
// ---------------------------------------------------------------------------
__global__ __launch_bounds__(256) void finalize_kernel(
    const float* __restrict__ proto,
    float* __restrict__ out_dist, float* __restrict__ out_idx,
    float* __restrict__ out_seq)
{
    int tid = threadIdx.x;
    int bb = tid >> 6;          // 0..3
    int p  = tid & 63;          // 0..63
    int b  = blockIdx.x * 4 + bb;

    float d = g_x2[b];
    #pragma unroll
    for (int ks = 0; ks < KSPLIT; ks++)
        d += g_part[((size_t)ks * BB + b) * PP + p];
    out_dist[b * PP + p] = d;

    // argmin over 64 lanes (2 warps), first-index tie-break
    float dv = d;
    unsigned iv = (unsigned)p;
    #pragma unroll
    for (int off = 16; off > 0; off >>= 1) {
        float od = __shfl_down_sync(0xffffffffu, dv, off);
        unsigned oi = __shfl_down_sync(0xffffffffu, iv, off);
        if (od < dv || (od == dv && oi < iv)) { dv = od; iv = oi; }
    }
    __shared__ float rd[8];
    __shared__ unsigned ri[8];
    __shared__ int s_idx[4];
    int w = tid >> 5;
    if ((tid & 31) == 0) { rd[w] = dv; ri[w] = iv; }
    __syncthreads();
    if (p == 0) {
        float d0 = rd[2 * bb]; unsigned i0 = ri[2 * bb];
        float d1 = rd[2 * bb + 1]; unsigned i1 = ri[2 * bb + 1];
        if (d1 < d0 || (d1 == d0 && i1 < i0)) { d0 = d1; i0 = i1; }
        s_idx[bb] = (int)i0;
        out_idx[b] = (float)i0;
    }
    __syncthreads();

    // gather: out_seq[b'] = proto[idx[b']] for this block's 4 batches
    #pragma unroll
    for (int q = 0; q < 4; q++) {
        int bq = blockIdx.x * 4 + q;
        const float2* src = (const float2*)(proto + (size_t)s_idx[q] * KK);
        float2* dst = (float2*)(out_seq + (size_t)bq * KK);
        for (int i = tid; i < KK / 2; i += 256) dst[i] = src[i];
    }
}

// ---------------------------------------------------------------------------
extern "C" void kernel_launch(void* const* d_in, const int* in_sizes, int n_in,
                              void* d_out, int out_size)
{
    const float* x     = (const float*)d_in[0];  // [512,365,10]
    const float* mask  = (const float*)d_in[1];  // [512,365]
    const int*   label = (const int*)  d_in[2];  // [512]
    const float* proto = (const float*)d_in[3];  // [64,365,10]

    float* out = (float*)d_out;
    float* out_seq  = out;                          // [512,365,10]
    float* out_in   = out_seq  + (size_t)BB * KK;   // [512,365,10]
    float* out_dist = out_in   + (size_t)BB * KK;   // [512,64]
    float* out_idx  = out_dist + (size_t)BB * PP;   // [512]
    float* out_lab  = out_idx  + BB;                // [512]
    float* out_mask = out_lab  + BB;                // [512,365]

    prep_kernel<<<BB + PP, 256>>>(x, mask, label, proto, out_in, out_mask, out_lab);
    gemm_kernel<<<dim3(BB / 64, KSPLIT), 256>>>(x, mask, proto);
    finalize_kernel<<<BB / 4, 256>>>(proto, out_dist, out_idx, out_seq);
}